// round 10
// baseline (speedup 1.0000x reference)
#include <cuda_runtime.h>

// ---------------------------------------------------------------------------
// SINDy autoencoder forward (batch-1, HBM-bound, ~545MB weights/call).
// Output: [z(16) | dz(16) | dzb(16) | xb(16384) | dxb(16384)] = 32816 f32
// R10: R4 big kernels + k_small; enc1/dec1 rewritten warp-per-row with
//      batched load groups to cut critical-path latency.
// ---------------------------------------------------------------------------

#define W0_OUT 4096
#define W0_IN  16384
#define W1_OUT 1024
#define LATENT 16
#define SINDY_DIM 984

__device__ float g_pre1[W0_OUT], g_u1[W0_OUT];
__device__ float g_pre2p[2 * W1_OUT], g_u2p[2 * W1_OUT];
__device__ float g_g1[1024],  g_p1[1024];
__device__ float g_q2[4096],  g_v2[4096];

__device__ __forceinline__ float sigf(float x) { return 1.0f / (1.0f + __expf(-x)); }
__device__ __forceinline__ float4 ldcs4(const float* p) { return __ldcs((const float4*)p); }

__device__ __forceinline__ void pdl_trigger() {
    asm volatile("griddepcontrol.launch_dependents;" ::: "memory");
}
__device__ __forceinline__ void pdl_wait() {
    asm volatile("griddepcontrol.wait;" ::: "memory");
}
__device__ __forceinline__ void l2_prefetch(const void* p) {
    asm volatile("prefetch.global.L2 [%0];" :: "l"(p));
}
template<int THREADS>
__device__ __forceinline__ void prefetch_tile(const float* base, int bytes) {
    const char* p = (const char*)base;
    for (int off = threadIdx.x * 128; off < bytes; off += THREADS * 128)
        l2_prefetch(p + off);
}

// ---------------------------------------------------------------------------
// Big dual matvec (R4-proven): outA[row]=W@a(+bias), outB[row]=W@b.
// ---------------------------------------------------------------------------
template<int KSTRIDE, int KCHUNK, int ROWS, int THREADS, bool SIG>
__device__ __forceinline__ void dual_body(
    const float* __restrict__ W,
    const float* __restrict__ av,
    const float* __restrict__ bv,
    const float* __restrict__ bias,
    float* __restrict__ outA,
    float* __restrict__ outB,
    int row0)
{
    constexpr int NW = THREADS / 32;
    constexpr int ITERS = KCHUNK / (THREADS * 4);
    const int tid = threadIdx.x;

    float accA[ROWS], accB[ROWS];
#pragma unroll
    for (int r = 0; r < ROWS; r++) { accA[r] = 0.0f; accB[r] = 0.0f; }

#pragma unroll 2
    for (int it = 0; it < ITERS; it++) {
        const int k = (it * THREADS + tid) * 4;
        float4 w4[ROWS];
#pragma unroll
        for (int r = 0; r < ROWS; r++)
            w4[r] = ldcs4(W + (size_t)r * KSTRIDE + k);
        float4 a4 = *(const float4*)(av + k);
        float4 b4 = *(const float4*)(bv + k);
        if (SIG) {
            float s;
            s = sigf(a4.x); b4.x *= s * (1.0f - s); a4.x = s;
            s = sigf(a4.y); b4.y *= s * (1.0f - s); a4.y = s;
            s = sigf(a4.z); b4.z *= s * (1.0f - s); a4.z = s;
            s = sigf(a4.w); b4.w *= s * (1.0f - s); a4.w = s;
        }
#pragma unroll
        for (int r = 0; r < ROWS; r++) {
            accA[r] = fmaf(w4[r].x, a4.x, accA[r]);
            accA[r] = fmaf(w4[r].y, a4.y, accA[r]);
            accA[r] = fmaf(w4[r].z, a4.z, accA[r]);
            accA[r] = fmaf(w4[r].w, a4.w, accA[r]);
            accB[r] = fmaf(w4[r].x, b4.x, accB[r]);
            accB[r] = fmaf(w4[r].y, b4.y, accB[r]);
            accB[r] = fmaf(w4[r].z, b4.z, accB[r]);
            accB[r] = fmaf(w4[r].w, b4.w, accB[r]);
        }
    }

    __shared__ float sA[NW][ROWS], sB[NW][ROWS];
    const int lane = tid & 31, warp = tid >> 5;
#pragma unroll
    for (int r = 0; r < ROWS; r++) {
        float vA = accA[r], vB = accB[r];
#pragma unroll
        for (int o = 16; o; o >>= 1) {
            vA += __shfl_xor_sync(0xffffffffu, vA, o);
            vB += __shfl_xor_sync(0xffffffffu, vB, o);
        }
        if (lane == 0) { sA[warp][r] = vA; sB[warp][r] = vB; }
    }
    __syncthreads();
    if (tid < ROWS) {
        float vA = 0.0f, vB = 0.0f;
#pragma unroll
        for (int w = 0; w < NW; w++) { vA += sA[w][tid]; vB += sB[w][tid]; }
        if (bias) vA += bias[row0 + tid];
        outA[row0 + tid] = vA;
        outB[row0 + tid] = vB;
    }
}

// enc L0 (256 MB, first in chain) — exact R4
__global__ void __launch_bounds__(256) k_enc0(
    const float* __restrict__ W, const float* __restrict__ x,
    const float* __restrict__ dx, const float* __restrict__ b)
{
    pdl_trigger();
    const int row0 = blockIdx.x * 4;
    dual_body<W0_IN, W0_IN, 4, 256, false>(
        W + (size_t)row0 * W0_IN, x, dx, b, g_pre1, g_u1, row0);
}

// ---------------------------------------------------------------------------
// enc L1 (16 MB), warp-per-row, split-K x2. grid (128, 2), 256 threads.
// Block stages sigmoid'd h1/t1 for its 2048-col split into smem once, then
// each warp computes one row-chunk with 4 batches of 4 LDG.128 (MLP=8+).
// ---------------------------------------------------------------------------
__global__ void __launch_bounds__(256) k_enc1(
    const float* __restrict__ W, const float* __restrict__ b)
{
    __shared__ float sh[2048], st[2048];
    pdl_trigger();
    const int tid   = threadIdx.x;
    const int lane  = tid & 31, warp = tid >> 5;   // 8 warps
    const int split = blockIdx.y;
    const int koff  = split * 2048;
    const int row   = blockIdx.x * 8 + warp;       // 0..1023
    const float* wr = W + (size_t)row * W0_OUT + koff;

    // prefetch this block's 8 row-chunks (8 x 8KB)
    {
        const float* base = W + (size_t)(blockIdx.x * 8) * W0_OUT + koff;
        for (int r = 0; r < 8; r++)
            prefetch_tile<256>(base + (size_t)r * W0_OUT, 8192);
    }
    pdl_wait();

    for (int i = tid; i < 2048; i += 256) {
        const int c = koff + i;
        float s = sigf(g_pre1[c]);
        sh[i] = s;
        st[i] = s * (1.0f - s) * g_u1[c];
    }
    __syncthreads();

    float accA = 0.0f, accB = 0.0f;
#pragma unroll
    for (int bt = 0; bt < 4; bt++) {
        float4 w4[4];
#pragma unroll
        for (int j = 0; j < 4; j++)
            w4[j] = ldcs4(wr + ((bt * 4 + j) * 32 + lane) * 4);
#pragma unroll
        for (int j = 0; j < 4; j++) {
            const int c = ((bt * 4 + j) * 32 + lane) * 4;
            accA = fmaf(w4[j].x, sh[c],     accA);
            accA = fmaf(w4[j].y, sh[c + 1], accA);
            accA = fmaf(w4[j].z, sh[c + 2], accA);
            accA = fmaf(w4[j].w, sh[c + 3], accA);
            accB = fmaf(w4[j].x, st[c],     accB);
            accB = fmaf(w4[j].y, st[c + 1], accB);
            accB = fmaf(w4[j].z, st[c + 2], accB);
            accB = fmaf(w4[j].w, st[c + 3], accB);
        }
    }
#pragma unroll
    for (int o = 16; o; o >>= 1) {
        accA += __shfl_xor_sync(0xffffffffu, accA, o);
        accB += __shfl_xor_sync(0xffffffffu, accB, o);
    }
    if (lane == 0) {
        if (split == 0) accA += b[row];
        g_pre2p[split * W1_OUT + row] = accA;
        g_u2p[split * W1_OUT + row]   = accB;
    }
}

// ---------------------------------------------------------------------------
// dec L1 (16 MB), warp-per-row. grid 512, 256 threads.
// g1/p1 staged to smem; weights in 2 batches of 4 LDG.128 per lane.
// ---------------------------------------------------------------------------
__global__ void __launch_bounds__(256) k_dec1(
    const float* __restrict__ W, const float* __restrict__ b)
{
    __shared__ float sg[1024], sp[1024];
    pdl_trigger();
    const int tid  = threadIdx.x;
    const int lane = tid & 31, warp = tid >> 5;    // 8 warps
    const int row  = blockIdx.x * 8 + warp;        // 0..4095
    const float* wr = W + (size_t)row * 1024;

    prefetch_tile<256>(W + (size_t)(blockIdx.x * 8) * 1024, 8 * 1024 * 4);
    pdl_wait();

    for (int i = tid; i < 1024; i += 256) {
        sg[i] = g_g1[i];
        sp[i] = g_p1[i];
    }
    __syncthreads();

    float accA = 0.0f, accB = 0.0f;
#pragma unroll
    for (int bt = 0; bt < 2; bt++) {
        float4 w4[4];
#pragma unroll
        for (int j = 0; j < 4; j++)
            w4[j] = ldcs4(wr + ((bt * 4 + j) * 32 + lane) * 4);
#pragma unroll
        for (int j = 0; j < 4; j++) {
            const int c = ((bt * 4 + j) * 32 + lane) * 4;
            accA = fmaf(w4[j].x, sg[c],     accA);
            accA = fmaf(w4[j].y, sg[c + 1], accA);
            accA = fmaf(w4[j].z, sg[c + 2], accA);
            accA = fmaf(w4[j].w, sg[c + 3], accA);
            accB = fmaf(w4[j].x, sp[c],     accB);
            accB = fmaf(w4[j].y, sp[c + 1], accB);
            accB = fmaf(w4[j].z, sp[c + 2], accB);
            accB = fmaf(w4[j].w, sp[c + 3], accB);
        }
    }
#pragma unroll
    for (int o = 16; o; o >>= 1) {
        accA += __shfl_xor_sync(0xffffffffu, accA, o);
        accB += __shfl_xor_sync(0xffffffffu, accB, o);
    }
    if (lane == 0) {
        g_q2[row] = accA + b[row];
        g_v2[row] = accB;
    }
}

// dec L2 (256 MB, last) — exact R4
__global__ void __launch_bounds__(256) k_dec2(
    const float* __restrict__ W, const float* __restrict__ b,
    float* __restrict__ out)
{
    const int row0 = blockIdx.x * 4;
    const float* Wt = W + (size_t)row0 * 4096;
    prefetch_tile<256>(Wt, 4 * 4096 * 4);
    pdl_wait();
    dual_body<4096, 4096, 4, 256, true>(
        Wt, g_q2, g_v2, b, out + 48, out + 48 + 16384, row0);
}

// ---------------------------------------------------------------------------
// Middle chain, one block, 512 threads, weights prefetched to smem (R4).
// ---------------------------------------------------------------------------
#define SM_WE2   0
#define SM_EW    16384
#define SM_WD0   32128
#define SM_H2    48512
#define SM_T2    49536
#define SM_THETA 50560
#define SM_FLOATS 51544
#define SM_BYTES (SM_FLOATS * 4)

__global__ void __launch_bounds__(512) k_small(
    const float* __restrict__ we_w2, const float* __restrict__ we_b2,
    const float* __restrict__ E_w,   const float* __restrict__ E_b,
    const float* __restrict__ wd_w0, const float* __restrict__ wd_b0,
    float* __restrict__ out)
{
    extern __shared__ float sm[];
    __shared__ float z[LATENT], dz[LATENT], dzb[LATENT];

    const int tid = threadIdx.x;
    const int lane = tid & 31, wid = tid >> 5;

    pdl_trigger();
    prefetch_tile<512>(we_w2, 16384 * 4);
    prefetch_tile<512>(E_w,   15744 * 4);
    prefetch_tile<512>(wd_w0, 16384 * 4);
    pdl_wait();

    for (int i = tid; i < 4096; i += 512)
        *(float4*)(sm + SM_WE2 + i * 4) = ldcs4(we_w2 + i * 4);
    for (int i = tid; i < 3936; i += 512)
        *(float4*)(sm + SM_EW + i * 4) = ldcs4(E_w + i * 4);
    for (int i = tid; i < 4096; i += 512)
        *(float4*)(sm + SM_WD0 + i * 4) = ldcs4(wd_w0 + i * 4);
    for (int i = tid; i < W1_OUT; i += 512) {
        float pre = g_pre2p[i] + g_pre2p[W1_OUT + i];
        float u   = g_u2p[i]   + g_u2p[W1_OUT + i];
        float s = sigf(pre);
        sm[SM_H2 + i] = s;
        sm[SM_T2 + i] = s * (1.0f - s) * u;
    }
    __syncthreads();

    {
        float az = 0.0f, ad = 0.0f;
        const float* wr = sm + SM_WE2 + wid * W1_OUT;
        for (int c = lane; c < W1_OUT; c += 32) {
            float w = wr[c];
            az = fmaf(w, sm[SM_H2 + c], az);
            ad = fmaf(w, sm[SM_T2 + c], ad);
        }
#pragma unroll
        for (int o = 16; o; o >>= 1) {
            az += __shfl_xor_sync(0xffffffffu, az, o);
            ad += __shfl_xor_sync(0xffffffffu, ad, o);
        }
        if (lane == 0) { z[wid] = az + we_b2[wid]; dz[wid] = ad; }
    }
    __syncthreads();

    if (tid < LATENT) { out[tid] = z[tid]; out[LATENT + tid] = dz[tid]; }

    for (int idx = tid; idx < SINDY_DIM; idx += 512) {
        float v;
        if (idx < 16) v = 1.0f;
        else if (idx < 32) v = z[idx - 16];
        else if (idx < 168) {
            int q = idx - 32, i = 0;
            for (;;) { int m = 16 - i; if (q < m) break; q -= m; i++; }
            v = z[i] * z[i + q];
        } else {
            int t = idx - 168, i = 0;
            for (;;) { int m = 16 - i; int c = m * (m + 1) / 2; if (t < c) break; t -= c; i++; }
            int j = i;
            for (;;) { int m = 16 - j; if (t < m) break; t -= m; j++; }
            v = z[i] * z[j] * z[j + t];
        }
        sm[SM_THETA + idx] = v;
    }
    __syncthreads();

    {
        float a = 0.0f;
        const float* er = sm + SM_EW + wid * SINDY_DIM;
        for (int c = lane; c < SINDY_DIM; c += 32)
            a = fmaf(er[c], sm[SM_THETA + c], a);
#pragma unroll
        for (int o = 16; o; o >>= 1)
            a += __shfl_xor_sync(0xffffffffu, a, o);
        if (lane == 0) dzb[wid] = a + E_b[wid];
    }
    __syncthreads();

    if (tid < LATENT) out[32 + tid] = dzb[tid];

    for (int row = tid; row < 1024; row += 512) {
        float a = wd_b0[row], bb = 0.0f;
        const float* wr = sm + SM_WD0 + row * LATENT;
#pragma unroll
        for (int c = 0; c < LATENT; c++) {
            float w = wr[c];
            a  = fmaf(w, z[c],   a);
            bb = fmaf(w, dzb[c], bb);
        }
        float s = sigf(a);
        g_g1[row] = s;
        g_p1[row] = s * (1.0f - s) * bb;
    }
}

// ---------------------------------------------------------------------------
extern "C" void kernel_launch(void* const* d_in, const int* in_sizes, int n_in,
                              void* d_out, int out_size)
{
    const float* x     = (const float*)d_in[0];
    const float* dx    = (const float*)d_in[1];
    const float* we_w0 = (const float*)d_in[3];
    const float* we_b0 = (const float*)d_in[4];
    const float* we_w1 = (const float*)d_in[5];
    const float* we_b1 = (const float*)d_in[6];
    const float* we_w2 = (const float*)d_in[7];
    const float* we_b2 = (const float*)d_in[8];
    const float* wd_w0 = (const float*)d_in[9];
    const float* wd_b0 = (const float*)d_in[10];
    const float* wd_w1 = (const float*)d_in[11];
    const float* wd_b1 = (const float*)d_in[12];
    const float* wd_w2 = (const float*)d_in[13];
    const float* wd_b2 = (const float*)d_in[14];
    const float* E_w   = (const float*)d_in[15];
    const float* E_b   = (const float*)d_in[16];
    float* out = (float*)d_out;

    cudaFuncSetAttribute(k_small, cudaFuncAttributeMaxDynamicSharedMemorySize, SM_BYTES);

    cudaLaunchAttribute attr[1];
    attr[0].id = cudaLaunchAttributeProgrammaticStreamSerialization;
    attr[0].val.programmaticStreamSerializationAllowed = 1;

    cudaLaunchConfig_t cfg{};
    cfg.blockDim = dim3(256, 1, 1);
    cfg.dynamicSmemBytes = 0;
    cfg.stream = 0;
    cfg.attrs = attr;
    cfg.numAttrs = 1;

    // 1) enc L0 (256 MB)
    cfg.gridDim = dim3(W0_OUT / 4, 1, 1);
    cudaLaunchKernelEx(&cfg, k_enc0, we_w0, x, dx, we_b0);

    // 2) enc L1 (16 MB, warp-per-row, split-K x2)
    cfg.gridDim = dim3(128, 2, 1);
    cudaLaunchKernelEx(&cfg, k_enc1, we_w1, we_b1);

    // 3) middle chain
    {
        cudaLaunchConfig_t cs = cfg;
        cs.gridDim = dim3(1, 1, 1);
        cs.blockDim = dim3(512, 1, 1);
        cs.dynamicSmemBytes = SM_BYTES;
        cudaLaunchKernelEx(&cs, k_small, we_w2, we_b2, E_w, E_b, wd_w0, wd_b0, out);
    }

    // 4) dec L1 (16 MB, warp-per-row)
    cfg.gridDim = dim3(512, 1, 1);
    cudaLaunchKernelEx(&cfg, k_dec1, wd_w1, wd_b1);

    // 5) dec L2 (256 MB)
    cfg.gridDim = dim3(16384 / 4, 1, 1);
    cudaLaunchKernelEx(&cfg, k_dec2, wd_w2, wd_b2, out);
}

// round 11
// speedup vs baseline: 1.0506x; 1.0506x over previous
#include <cuda_runtime.h>

// ---------------------------------------------------------------------------
// SINDy autoencoder forward (batch-1, HBM-bound, ~545MB weights/call).
// Output: [z(16) | dz(16) | dzb(16) | xb(16384) | dxb(16384)] = 32816 f32
// R11: exact R4 bodies; k_small folded into the LAST enc1 block via a
//      self-resetting done-counter (4 launches instead of 5; dec1's weight
//      prefetch overlaps the small chain).
// ---------------------------------------------------------------------------

#define W0_OUT 4096
#define W0_IN  16384
#define W1_OUT 1024
#define LATENT 16
#define SINDY_DIM 984

__device__ float g_pre1[W0_OUT], g_u1[W0_OUT];
__device__ float g_pre2p[2 * W1_OUT], g_u2p[2 * W1_OUT];
__device__ float g_g1[1024],  g_p1[1024];
__device__ float g_q2[4096],  g_v2[4096];
__device__ unsigned g_done;          // enc1 completion ticket counter

__device__ __forceinline__ float sigf(float x) { return 1.0f / (1.0f + __expf(-x)); }
__device__ __forceinline__ float4 ldcs4(const float* p) { return __ldcs((const float4*)p); }

__device__ __forceinline__ void pdl_trigger() {
    asm volatile("griddepcontrol.launch_dependents;" ::: "memory");
}
__device__ __forceinline__ void pdl_wait() {
    asm volatile("griddepcontrol.wait;" ::: "memory");
}
__device__ __forceinline__ void l2_prefetch(const void* p) {
    asm volatile("prefetch.global.L2 [%0];" :: "l"(p));
}
template<int THREADS>
__device__ __forceinline__ void prefetch_tile(const float* base, int bytes) {
    const char* p = (const char*)base;
    for (int off = threadIdx.x * 128; off < bytes; off += THREADS * 128)
        l2_prefetch(p + off);
}

// ---------------------------------------------------------------------------
// Dual matvec (R4-proven): outA[row]=W@a(+bias), outB[row]=W@b.
// ---------------------------------------------------------------------------
template<int KSTRIDE, int KCHUNK, int ROWS, int THREADS, bool SIG>
__device__ __forceinline__ void dual_body(
    const float* __restrict__ W,
    const float* __restrict__ av,
    const float* __restrict__ bv,
    const float* __restrict__ bias,
    float* __restrict__ outA,
    float* __restrict__ outB,
    int row0)
{
    constexpr int NW = THREADS / 32;
    constexpr int ITERS = KCHUNK / (THREADS * 4);
    const int tid = threadIdx.x;

    float accA[ROWS], accB[ROWS];
#pragma unroll
    for (int r = 0; r < ROWS; r++) { accA[r] = 0.0f; accB[r] = 0.0f; }

#pragma unroll 2
    for (int it = 0; it < ITERS; it++) {
        const int k = (it * THREADS + tid) * 4;
        float4 w4[ROWS];
#pragma unroll
        for (int r = 0; r < ROWS; r++)
            w4[r] = ldcs4(W + (size_t)r * KSTRIDE + k);
        float4 a4 = *(const float4*)(av + k);
        float4 b4 = *(const float4*)(bv + k);
        if (SIG) {
            float s;
            s = sigf(a4.x); b4.x *= s * (1.0f - s); a4.x = s;
            s = sigf(a4.y); b4.y *= s * (1.0f - s); a4.y = s;
            s = sigf(a4.z); b4.z *= s * (1.0f - s); a4.z = s;
            s = sigf(a4.w); b4.w *= s * (1.0f - s); a4.w = s;
        }
#pragma unroll
        for (int r = 0; r < ROWS; r++) {
            accA[r] = fmaf(w4[r].x, a4.x, accA[r]);
            accA[r] = fmaf(w4[r].y, a4.y, accA[r]);
            accA[r] = fmaf(w4[r].z, a4.z, accA[r]);
            accA[r] = fmaf(w4[r].w, a4.w, accA[r]);
            accB[r] = fmaf(w4[r].x, b4.x, accB[r]);
            accB[r] = fmaf(w4[r].y, b4.y, accB[r]);
            accB[r] = fmaf(w4[r].z, b4.z, accB[r]);
            accB[r] = fmaf(w4[r].w, b4.w, accB[r]);
        }
    }

    __shared__ float sA[NW][ROWS], sB[NW][ROWS];
    const int lane = tid & 31, warp = tid >> 5;
#pragma unroll
    for (int r = 0; r < ROWS; r++) {
        float vA = accA[r], vB = accB[r];
#pragma unroll
        for (int o = 16; o; o >>= 1) {
            vA += __shfl_xor_sync(0xffffffffu, vA, o);
            vB += __shfl_xor_sync(0xffffffffu, vB, o);
        }
        if (lane == 0) { sA[warp][r] = vA; sB[warp][r] = vB; }
    }
    __syncthreads();
    if (tid < ROWS) {
        float vA = 0.0f, vB = 0.0f;
#pragma unroll
        for (int w = 0; w < NW; w++) { vA += sA[w][tid]; vB += sB[w][tid]; }
        if (bias) vA += bias[row0 + tid];
        outA[row0 + tid] = vA;
        outB[row0 + tid] = vB;
    }
}

// enc L0 (256 MB, first in chain) — exact R4
__global__ void __launch_bounds__(256) k_enc0(
    const float* __restrict__ W, const float* __restrict__ x,
    const float* __restrict__ dx, const float* __restrict__ b)
{
    pdl_trigger();
    const int row0 = blockIdx.x * 4;
    dual_body<W0_IN, W0_IN, 4, 256, false>(
        W + (size_t)row0 * W0_IN, x, dx, b, g_pre1, g_u1, row0);
}

// ---------------------------------------------------------------------------
// enc L1 (16 MB, split-K x2) + FUSED small chain in the last-finishing block.
// grid (256, 2) = 512 blocks, 256 threads.
// ---------------------------------------------------------------------------
__global__ void __launch_bounds__(256) k_enc1s(
    const float* __restrict__ W,     const float* __restrict__ b,
    const float* __restrict__ we_w2, const float* __restrict__ we_b2,
    const float* __restrict__ E_w,   const float* __restrict__ E_b,
    const float* __restrict__ wd_w0, const float* __restrict__ wd_b0,
    float* __restrict__ out)
{
    pdl_trigger();
    const int tid   = threadIdx.x;
    const int row0  = blockIdx.x * 4;
    const int split = blockIdx.y;
    const int koff  = split * 2048;
    const float* Wt = W + (size_t)row0 * W0_OUT + koff;

    // prefetch own weight tile (R4); block (0,0) also prefetches small mats
#pragma unroll
    for (int r = 0; r < 4; r++)
        prefetch_tile<256>(Wt + (size_t)r * W0_OUT, 8192);
    if (blockIdx.x == 0 && split == 0) {
        prefetch_tile<256>(we_w2, 16384 * 4);
        prefetch_tile<256>(E_w,   15744 * 4);
        prefetch_tile<256>(wd_w0, 16384 * 4);
    }
    pdl_wait();

    dual_body<W0_OUT, 2048, 4, 256, true>(
        Wt, g_pre1 + koff, g_u1 + koff,
        split == 0 ? b : nullptr,
        g_pre2p + split * W1_OUT, g_u2p + split * W1_OUT, row0);

    // ---- ticket: last block runs the small chain ----
    __shared__ unsigned s_ticket;
    __threadfence();                               // release g_pre2p/g_u2p
    __syncthreads();
    if (tid == 0) s_ticket = atomicAdd(&g_done, 1u);
    __syncthreads();
    if (s_ticket != 511u) return;
    __threadfence();                               // acquire all blocks' writes

    // ================= small chain (256 threads) =================
    __shared__ float sh2[W1_OUT], st2[W1_OUT];
    __shared__ float theta[SINDY_DIM];
    __shared__ float z[LATENT], dz[LATENT], dzb[LATENT];
    const int lane = tid & 31, warp = tid >> 5;    // 8 warps

    // h2/t2 from partials
    for (int i = tid; i < W1_OUT; i += 256) {
        float pre = g_pre2p[i] + g_pre2p[W1_OUT + i];
        float u   = g_u2p[i]   + g_u2p[W1_OUT + i];
        float s = sigf(pre);
        sh2[i] = s;
        st2[i] = s * (1.0f - s) * u;
    }
    __syncthreads();

    // z, dz: 8 warps x 2 rows (we_w2 L2-hot)
    for (int r = warp; r < LATENT; r += 8) {
        float az = 0.0f, ad = 0.0f;
        const float* wr = we_w2 + (size_t)r * W1_OUT;
        for (int c = lane * 4; c < W1_OUT; c += 128) {
            float4 w4 = *(const float4*)(wr + c);
            az = fmaf(w4.x, sh2[c],     az); az = fmaf(w4.y, sh2[c + 1], az);
            az = fmaf(w4.z, sh2[c + 2], az); az = fmaf(w4.w, sh2[c + 3], az);
            ad = fmaf(w4.x, st2[c],     ad); ad = fmaf(w4.y, st2[c + 1], ad);
            ad = fmaf(w4.z, st2[c + 2], ad); ad = fmaf(w4.w, st2[c + 3], ad);
        }
#pragma unroll
        for (int o = 16; o; o >>= 1) {
            az += __shfl_xor_sync(0xffffffffu, az, o);
            ad += __shfl_xor_sync(0xffffffffu, ad, o);
        }
        if (lane == 0) { z[r] = az + we_b2[r]; dz[r] = ad; }
    }
    __syncthreads();

    if (tid < LATENT) { out[tid] = z[tid]; out[LATENT + tid] = dz[tid]; }

    // theta
    for (int idx = tid; idx < SINDY_DIM; idx += 256) {
        float v;
        if (idx < 16) v = 1.0f;
        else if (idx < 32) v = z[idx - 16];
        else if (idx < 168) {
            int q = idx - 32, i = 0;
            for (;;) { int m = 16 - i; if (q < m) break; q -= m; i++; }
            v = z[i] * z[i + q];
        } else {
            int t = idx - 168, i = 0;
            for (;;) { int m = 16 - i; int c = m * (m + 1) / 2; if (t < c) break; t -= c; i++; }
            int j = i;
            for (;;) { int m = 16 - j; if (t < m) break; t -= m; j++; }
            v = z[i] * z[j] * z[j + t];
        }
        theta[idx] = v;
    }
    __syncthreads();

    // dzb: 8 warps x 2 rows (E_w L2-hot)
    for (int r = warp; r < LATENT; r += 8) {
        float a = 0.0f;
        const float* er = E_w + (size_t)r * SINDY_DIM;
        for (int c = lane; c < SINDY_DIM; c += 32)
            a = fmaf(er[c], theta[c], a);
#pragma unroll
        for (int o = 16; o; o >>= 1)
            a += __shfl_xor_sync(0xffffffffu, a, o);
        if (lane == 0) dzb[r] = a + E_b[r];
    }
    __syncthreads();

    if (tid < LATENT) out[32 + tid] = dzb[tid];

    // dec L0 + activation -> g_g1/g_p1 (wd_w0 L2-hot)
    for (int row = tid; row < 1024; row += 256) {
        float a = wd_b0[row], bb = 0.0f;
        const float* wr = wd_w0 + (size_t)row * LATENT;
#pragma unroll
        for (int c = 0; c < LATENT; c++) {
            float w = wr[c];
            a  = fmaf(w, z[c],   a);
            bb = fmaf(w, dzb[c], bb);
        }
        float s = sigf(a);
        g_g1[row] = s;
        g_p1[row] = s * (1.0f - s) * bb;
    }

    if (tid == 0) g_done = 0u;    // reset for next graph replay
    __threadfence();
}

// dec L1 (16 MB) — exact R4
__global__ void __launch_bounds__(256) k_dec1(
    const float* __restrict__ W, const float* __restrict__ b)
{
    pdl_trigger();
    const int row0 = blockIdx.x * 4;
    const float* Wt = W + (size_t)row0 * 1024;
    prefetch_tile<256>(Wt, 4 * 1024 * 4);
    pdl_wait();
    dual_body<1024, 1024, 4, 256, false>(
        Wt, g_g1, g_p1, b, g_q2, g_v2, row0);
}

// dec L2 (256 MB, last) — exact R4
__global__ void __launch_bounds__(256) k_dec2(
    const float* __restrict__ W, const float* __restrict__ b,
    float* __restrict__ out)
{
    const int row0 = blockIdx.x * 4;
    const float* Wt = W + (size_t)row0 * 4096;
    prefetch_tile<256>(Wt, 4 * 4096 * 4);
    pdl_wait();
    dual_body<4096, 4096, 4, 256, true>(
        Wt, g_q2, g_v2, b, out + 48, out + 48 + 16384, row0);
}

// ---------------------------------------------------------------------------
extern "C" void kernel_launch(void* const* d_in, const int* in_sizes, int n_in,
                              void* d_out, int out_size)
{
    const float* x     = (const float*)d_in[0];
    const float* dx    = (const float*)d_in[1];
    const float* we_w0 = (const float*)d_in[3];
    const float* we_b0 = (const float*)d_in[4];
    const float* we_w1 = (const float*)d_in[5];
    const float* we_b1 = (const float*)d_in[6];
    const float* we_w2 = (const float*)d_in[7];
    const float* we_b2 = (const float*)d_in[8];
    const float* wd_w0 = (const float*)d_in[9];
    const float* wd_b0 = (const float*)d_in[10];
    const float* wd_w1 = (const float*)d_in[11];
    const float* wd_b1 = (const float*)d_in[12];
    const float* wd_w2 = (const float*)d_in[13];
    const float* wd_b2 = (const float*)d_in[14];
    const float* E_w   = (const float*)d_in[15];
    const float* E_b   = (const float*)d_in[16];
    float* out = (float*)d_out;

    cudaLaunchAttribute attr[1];
    attr[0].id = cudaLaunchAttributeProgrammaticStreamSerialization;
    attr[0].val.programmaticStreamSerializationAllowed = 1;

    cudaLaunchConfig_t cfg{};
    cfg.blockDim = dim3(256, 1, 1);
    cfg.dynamicSmemBytes = 0;
    cfg.stream = 0;
    cfg.attrs = attr;
    cfg.numAttrs = 1;

    // 1) enc L0 (256 MB)
    cfg.gridDim = dim3(W0_OUT / 4, 1, 1);
    cudaLaunchKernelEx(&cfg, k_enc0, we_w0, x, dx, we_b0);

    // 2) enc L1 + fused small chain (16 MB + 0.2 MB)
    cfg.gridDim = dim3(W1_OUT / 4, 2, 1);
    cudaLaunchKernelEx(&cfg, k_enc1s, we_w1, we_b1,
                       we_w2, we_b2, E_w, E_b, wd_w0, wd_b0, out);

    // 3) dec L1 (16 MB)
    cfg.gridDim = dim3(4096 / 4, 1, 1);
    cudaLaunchKernelEx(&cfg, k_dec1, wd_w1, wd_b1);

    // 4) dec L2 (256 MB)
    cfg.gridDim = dim3(16384 / 4, 1, 1);
    cudaLaunchKernelEx(&cfg, k_dec2, wd_w2, wd_b2, out);
}

// round 12
// speedup vs baseline: 1.0796x; 1.0276x over previous
#include <cuda_runtime.h>

// ---------------------------------------------------------------------------
// SINDy autoencoder forward (batch-1, HBM-bound, ~545MB weights/call).
// Output: [z(16) | dz(16) | dzb(16) | xb(16384) | dxb(16384)] = 32816 f32
// R12: R4 structure; all sigmoid activations hoisted to producer epilogues
//      so both 256MB streaming loops are pure FMA (lower regs, no MUFU).
// ---------------------------------------------------------------------------

#define W0_OUT 4096
#define W0_IN  16384
#define W1_OUT 1024
#define LATENT 16
#define SINDY_DIM 984

__device__ float g_h1[W0_OUT], g_t1[W0_OUT];             // enc L0 ACTIVATED outputs
__device__ float g_pre2p[2 * W1_OUT], g_u2p[2 * W1_OUT]; // enc L1 partials (raw)
__device__ float g_g1[1024],  g_p1[1024];                // dec L0 activated
__device__ float g_g2[4096],  g_p2[4096];                // dec L1 ACTIVATED outputs

__device__ __forceinline__ float sigf(float x) { return 1.0f / (1.0f + __expf(-x)); }
__device__ __forceinline__ float4 ldcs4(const float* p) { return __ldcs((const float4*)p); }

__device__ __forceinline__ void pdl_trigger() {
    asm volatile("griddepcontrol.launch_dependents;" ::: "memory");
}
__device__ __forceinline__ void pdl_wait() {
    asm volatile("griddepcontrol.wait;" ::: "memory");
}
__device__ __forceinline__ void l2_prefetch(const void* p) {
    asm volatile("prefetch.global.L2 [%0];" :: "l"(p));
}
template<int THREADS>
__device__ __forceinline__ void prefetch_tile(const float* base, int bytes) {
    const char* p = (const char*)base;
    for (int off = threadIdx.x * 128; off < bytes; off += THREADS * 128)
        l2_prefetch(p + off);
}

// ---------------------------------------------------------------------------
// Dual matvec, pure-FMA inner loop. Epilogue optionally applies sigmoid:
//   ACT=false: outA = W@a (+bias), outB = W@b
//   ACT=true : s = sig(W@a + bias); outA = s; outB = s*(1-s)*(W@b)
// ---------------------------------------------------------------------------
template<int KSTRIDE, int KCHUNK, int ROWS, int THREADS, bool ACT>
__device__ __forceinline__ void dual_body(
    const float* __restrict__ W,
    const float* __restrict__ av,
    const float* __restrict__ bv,
    const float* __restrict__ bias,
    float* __restrict__ outA,
    float* __restrict__ outB,
    int row0)
{
    constexpr int NW = THREADS / 32;
    constexpr int ITERS = KCHUNK / (THREADS * 4);
    const int tid = threadIdx.x;

    float accA[ROWS], accB[ROWS];
#pragma unroll
    for (int r = 0; r < ROWS; r++) { accA[r] = 0.0f; accB[r] = 0.0f; }

#pragma unroll 2
    for (int it = 0; it < ITERS; it++) {
        const int k = (it * THREADS + tid) * 4;
        float4 w4[ROWS];
#pragma unroll
        for (int r = 0; r < ROWS; r++)
            w4[r] = ldcs4(W + (size_t)r * KSTRIDE + k);
        const float4 a4 = *(const float4*)(av + k);
        const float4 b4 = *(const float4*)(bv + k);
#pragma unroll
        for (int r = 0; r < ROWS; r++) {
            accA[r] = fmaf(w4[r].x, a4.x, accA[r]);
            accA[r] = fmaf(w4[r].y, a4.y, accA[r]);
            accA[r] = fmaf(w4[r].z, a4.z, accA[r]);
            accA[r] = fmaf(w4[r].w, a4.w, accA[r]);
            accB[r] = fmaf(w4[r].x, b4.x, accB[r]);
            accB[r] = fmaf(w4[r].y, b4.y, accB[r]);
            accB[r] = fmaf(w4[r].z, b4.z, accB[r]);
            accB[r] = fmaf(w4[r].w, b4.w, accB[r]);
        }
    }

    __shared__ float sA[NW][ROWS], sB[NW][ROWS];
    const int lane = tid & 31, warp = tid >> 5;
#pragma unroll
    for (int r = 0; r < ROWS; r++) {
        float vA = accA[r], vB = accB[r];
#pragma unroll
        for (int o = 16; o; o >>= 1) {
            vA += __shfl_xor_sync(0xffffffffu, vA, o);
            vB += __shfl_xor_sync(0xffffffffu, vB, o);
        }
        if (lane == 0) { sA[warp][r] = vA; sB[warp][r] = vB; }
    }
    __syncthreads();
    if (tid < ROWS) {
        float vA = 0.0f, vB = 0.0f;
#pragma unroll
        for (int w = 0; w < NW; w++) { vA += sA[w][tid]; vB += sB[w][tid]; }
        if (bias) vA += bias[row0 + tid];
        if (ACT) {
            float s = sigf(vA);
            outA[row0 + tid] = s;
            outB[row0 + tid] = s * (1.0f - s) * vB;
        } else {
            outA[row0 + tid] = vA;
            outB[row0 + tid] = vB;
        }
    }
}

// enc L0 (256 MB, first in chain): h1 = sig(W0@x + b0); t1 = sig'*(W0@dx)
__global__ void __launch_bounds__(256) k_enc0(
    const float* __restrict__ W, const float* __restrict__ x,
    const float* __restrict__ dx, const float* __restrict__ b)
{
    pdl_trigger();
    const int row0 = blockIdx.x * 4;
    dual_body<W0_IN, W0_IN, 4, 256, true>(
        W + (size_t)row0 * W0_IN, x, dx, b, g_h1, g_t1, row0);
}

// enc L1, split-K x2 (16 MB): raw partials from ACTIVATED h1/t1
__global__ void __launch_bounds__(256) k_enc1(
    const float* __restrict__ W, const float* __restrict__ b)
{
    pdl_trigger();
    const int row0  = blockIdx.x * 4;
    const int split = blockIdx.y;
    const int koff  = split * 2048;
    const float* Wt = W + (size_t)row0 * W0_OUT + koff;
#pragma unroll
    for (int r = 0; r < 4; r++)
        prefetch_tile<256>(Wt + (size_t)r * W0_OUT, 8192);
    pdl_wait();
    dual_body<W0_OUT, 2048, 4, 256, false>(
        Wt, g_h1 + koff, g_t1 + koff,
        split == 0 ? b : nullptr,
        g_pre2p + split * W1_OUT, g_u2p + split * W1_OUT, row0);
}

// dec L1 (16 MB): g2 = sig(Wd1@g1 + bd1); p2 = sig'*(Wd1@p1)
__global__ void __launch_bounds__(256) k_dec1(
    const float* __restrict__ W, const float* __restrict__ b)
{
    pdl_trigger();
    const int row0 = blockIdx.x * 4;
    const float* Wt = W + (size_t)row0 * 1024;
    prefetch_tile<256>(Wt, 4 * 1024 * 4);
    pdl_wait();
    dual_body<1024, 1024, 4, 256, true>(
        Wt, g_g1, g_p1, b, g_g2, g_p2, row0);
}

// dec L2 (256 MB, last): xb = Wd2@g2 + bd2; dxb = Wd2@p2 — pure FMA loop
__global__ void __launch_bounds__(256) k_dec2(
    const float* __restrict__ W, const float* __restrict__ b,
    float* __restrict__ out)
{
    const int row0 = blockIdx.x * 4;
    const float* Wt = W + (size_t)row0 * 4096;
    prefetch_tile<256>(Wt, 4 * 4096 * 4);
    pdl_wait();
    dual_body<4096, 4096, 4, 256, false>(
        Wt, g_g2, g_p2, b, out + 48, out + 48 + 16384, row0);
}

// ---------------------------------------------------------------------------
// Middle chain, one block, 512 threads, weights prefetched to smem (R4).
// ---------------------------------------------------------------------------
#define SM_WE2   0
#define SM_EW    16384
#define SM_WD0   32128
#define SM_H2    48512
#define SM_T2    49536
#define SM_THETA 50560
#define SM_FLOATS 51544
#define SM_BYTES (SM_FLOATS * 4)

__global__ void __launch_bounds__(512) k_small(
    const float* __restrict__ we_w2, const float* __restrict__ we_b2,
    const float* __restrict__ E_w,   const float* __restrict__ E_b,
    const float* __restrict__ wd_w0, const float* __restrict__ wd_b0,
    float* __restrict__ out)
{
    extern __shared__ float sm[];
    __shared__ float z[LATENT], dz[LATENT], dzb[LATENT];

    const int tid = threadIdx.x;
    const int lane = tid & 31, wid = tid >> 5;

    pdl_trigger();
    prefetch_tile<512>(we_w2, 16384 * 4);
    prefetch_tile<512>(E_w,   15744 * 4);
    prefetch_tile<512>(wd_w0, 16384 * 4);
    pdl_wait();

    for (int i = tid; i < 4096; i += 512)
        *(float4*)(sm + SM_WE2 + i * 4) = ldcs4(we_w2 + i * 4);
    for (int i = tid; i < 3936; i += 512)
        *(float4*)(sm + SM_EW + i * 4) = ldcs4(E_w + i * 4);
    for (int i = tid; i < 4096; i += 512)
        *(float4*)(sm + SM_WD0 + i * 4) = ldcs4(wd_w0 + i * 4);
    for (int i = tid; i < W1_OUT; i += 512) {
        float pre = g_pre2p[i] + g_pre2p[W1_OUT + i];
        float u   = g_u2p[i]   + g_u2p[W1_OUT + i];
        float s = sigf(pre);
        sm[SM_H2 + i] = s;
        sm[SM_T2 + i] = s * (1.0f - s) * u;
    }
    __syncthreads();

    {
        float az = 0.0f, ad = 0.0f;
        const float* wr = sm + SM_WE2 + wid * W1_OUT;
        for (int c = lane; c < W1_OUT; c += 32) {
            float w = wr[c];
            az = fmaf(w, sm[SM_H2 + c], az);
            ad = fmaf(w, sm[SM_T2 + c], ad);
        }
#pragma unroll
        for (int o = 16; o; o >>= 1) {
            az += __shfl_xor_sync(0xffffffffu, az, o);
            ad += __shfl_xor_sync(0xffffffffu, ad, o);
        }
        if (lane == 0) { z[wid] = az + we_b2[wid]; dz[wid] = ad; }
    }
    __syncthreads();

    if (tid < LATENT) { out[tid] = z[tid]; out[LATENT + tid] = dz[tid]; }

    for (int idx = tid; idx < SINDY_DIM; idx += 512) {
        float v;
        if (idx < 16) v = 1.0f;
        else if (idx < 32) v = z[idx - 16];
        else if (idx < 168) {
            int q = idx - 32, i = 0;
            for (;;) { int m = 16 - i; if (q < m) break; q -= m; i++; }
            v = z[i] * z[i + q];
        } else {
            int t = idx - 168, i = 0;
            for (;;) { int m = 16 - i; int c = m * (m + 1) / 2; if (t < c) break; t -= c; i++; }
            int j = i;
            for (;;) { int m = 16 - j; if (t < m) break; t -= m; j++; }
            v = z[i] * z[j] * z[j + t];
        }
        sm[SM_THETA + idx] = v;
    }
    __syncthreads();

    {
        float a = 0.0f;
        const float* er = sm + SM_EW + wid * SINDY_DIM;
        for (int c = lane; c < SINDY_DIM; c += 32)
            a = fmaf(er[c], sm[SM_THETA + c], a);
#pragma unroll
        for (int o = 16; o; o >>= 1)
            a += __shfl_xor_sync(0xffffffffu, a, o);
        if (lane == 0) dzb[wid] = a + E_b[wid];
    }
    __syncthreads();

    if (tid < LATENT) out[32 + tid] = dzb[tid];

    for (int row = tid; row < 1024; row += 512) {
        float a = wd_b0[row], bb = 0.0f;
        const float* wr = sm + SM_WD0 + row * LATENT;
#pragma unroll
        for (int c = 0; c < LATENT; c++) {
            float w = wr[c];
            a  = fmaf(w, z[c],   a);
            bb = fmaf(w, dzb[c], bb);
        }
        float s = sigf(a);
        g_g1[row] = s;
        g_p1[row] = s * (1.0f - s) * bb;
    }
}

// ---------------------------------------------------------------------------
extern "C" void kernel_launch(void* const* d_in, const int* in_sizes, int n_in,
                              void* d_out, int out_size)
{
    const float* x     = (const float*)d_in[0];
    const float* dx    = (const float*)d_in[1];
    const float* we_w0 = (const float*)d_in[3];
    const float* we_b0 = (const float*)d_in[4];
    const float* we_w1 = (const float*)d_in[5];
    const float* we_b1 = (const float*)d_in[6];
    const float* we_w2 = (const float*)d_in[7];
    const float* we_b2 = (const float*)d_in[8];
    const float* wd_w0 = (const float*)d_in[9];
    const float* wd_b0 = (const float*)d_in[10];
    const float* wd_w1 = (const float*)d_in[11];
    const float* wd_b1 = (const float*)d_in[12];
    const float* wd_w2 = (const float*)d_in[13];
    const float* wd_b2 = (const float*)d_in[14];
    const float* E_w   = (const float*)d_in[15];
    const float* E_b   = (const float*)d_in[16];
    float* out = (float*)d_out;

    cudaFuncSetAttribute(k_small, cudaFuncAttributeMaxDynamicSharedMemorySize, SM_BYTES);

    cudaLaunchAttribute attr[1];
    attr[0].id = cudaLaunchAttributeProgrammaticStreamSerialization;
    attr[0].val.programmaticStreamSerializationAllowed = 1;

    cudaLaunchConfig_t cfg{};
    cfg.blockDim = dim3(256, 1, 1);
    cfg.dynamicSmemBytes = 0;
    cfg.stream = 0;
    cfg.attrs = attr;
    cfg.numAttrs = 1;

    // 1) enc L0 (256 MB), activation fused into epilogue
    cfg.gridDim = dim3(W0_OUT / 4, 1, 1);
    cudaLaunchKernelEx(&cfg, k_enc0, we_w0, x, dx, we_b0);

    // 2) enc L1 (16 MB, split-K x2), pure FMA
    cfg.gridDim = dim3(W1_OUT / 4, 2, 1);
    cudaLaunchKernelEx(&cfg, k_enc1, we_w1, we_b1);

    // 3) middle chain
    {
        cudaLaunchConfig_t cs = cfg;
        cs.gridDim = dim3(1, 1, 1);
        cs.blockDim = dim3(512, 1, 1);
        cs.dynamicSmemBytes = SM_BYTES;
        cudaLaunchKernelEx(&cs, k_small, we_w2, we_b2, E_w, E_b, wd_w0, wd_b0, out);
    }

    // 4) dec L1 (16 MB), activation fused into epilogue
    cfg.gridDim = dim3(4096 / 4, 1, 1);
    cudaLaunchKernelEx(&cfg, k_dec1, wd_w1, wd_b1);

    // 5) dec L2 (256 MB), pure FMA
    cfg.gridDim = dim3(16384 / 4, 1, 1);
    cudaLaunchKernelEx(&cfg, k_dec2, wd_w2, wd_b2, out);
}